// round 15
// baseline (speedup 1.0000x reference)
#include <cuda_runtime.h>
#include <cuda_bf16.h>
#include <cuda_fp16.h>
#include <cstdint>
#include <cfloat>

#define N_ROWS 65536
#define DIM    1024
#define KCB    8192

#define WINDOW   0.40f     // candidate window (fp16 store err + bf16 GEMM noise, >2x margin)
#define TAU3     2.0e-3f   // full-refine fp32->fp64 shortlist window
#define WLC_CAP  32768
#define WLF_CAP  1024
#define CAND_CAP 8
#define MAX_CAND 64

#define BM 128
#define BN 128
#define KC 64
#define N_TILES (KCB / BN)                        // 64
#define CHUNKS_PER_TILE (DIM / KC)                // 16
#define TOTAL_CHUNKS (N_TILES * CHUNKS_PER_TILE)  // 1024
#define GEMM_THREADS 256

// row = 8192 halves = 16384 bytes = 1024 x uint4
#define ROW_U4 1024

// ---- hmma1 SMEM: 2 stages + 2KB min-reduce scratch ----
#define H1_STAGE   32768
#define H1_A       0
#define H1_B       16384
#define H1_MIN     65536                          // float[128*4]
#define H1_SMEM    (65536 + 2048)                 // 67584

// ---- scratch (__device__ globals; allocation-free rule) ----
__device__ __nv_bfloat16 g_zh[(size_t)N_ROWS * DIM];   // 128 MB
__device__ __nv_bfloat16 g_cbh[(size_t)KCB * DIM];     // 16 MB
__device__ float         g_cbT[(size_t)KCB * DIM];     // 32 MB
__device__ __half        g_dots[(size_t)N_ROWS * KCB]; // 1 GB dot matrix (fp16)
__device__ float g_rowmin[N_ROWS];                     // per-row fp32 min (from GEMM accs)
__device__ int   g_cand[(size_t)N_ROWS * CAND_CAP];    // per-row candidates
__device__ int   g_ccnt[N_ROWS];
__device__ int   g_argmin[N_ROWS];
__device__ int   g_wlc[WLC_CAP];
__device__ int   g_wlc_count;
__device__ int   g_wlf[WLF_CAP];
__device__ int   g_wlf_count;

// ============================ helpers ============================
__device__ __forceinline__ uint32_t smem_to_u32(const void* p) {
    uint32_t a;
    asm("{ .reg .u64 t; cvta.to.shared.u64 t, %1; cvt.u32.u64 %0, t; }" : "=r"(a) : "l"(p));
    return a;
}
#define SWZ128(o) ((o) ^ (((o) >> 3) & 0x70))

#define CP_ASYNC16(sm, g) \
    asm volatile("cp.async.cg.shared.global [%0], [%1], 16;" :: "r"(sm), "l"(g) : "memory")
#define CP_COMMIT()  asm volatile("cp.async.commit_group;" ::: "memory")
#define CP_WAIT1()   asm volatile("cp.async.wait_group 1;" ::: "memory")
#define CP_WAIT0()   asm volatile("cp.async.wait_group 0;" ::: "memory")

#define LDMATRIX_X4(r0, r1, r2, r3, a) \
    asm volatile("ldmatrix.sync.aligned.m8n8.x4.shared.b16 {%0,%1,%2,%3}, [%4];" \
                 : "=r"(r0), "=r"(r1), "=r"(r2), "=r"(r3) : "r"(a))

#define MMA_BF16(c0, c1, c2, c3, a0, a1, a2, a3, b0, b1) \
    asm volatile("mma.sync.aligned.m16n8k16.row.col.f32.bf16.bf16.f32 " \
                 "{%0,%1,%2,%3}, {%4,%5,%6,%7}, {%8,%9}, {%0,%1,%2,%3};" \
                 : "+f"(c0), "+f"(c1), "+f"(c2), "+f"(c3) \
                 : "r"(a0), "r"(a1), "r"(a2), "r"(a3), "r"(b0), "r"(b1))

// ---------------------------------------------------------------------------
// Prep 1: transpose codebook -> cbT fp32 + cbh bf16; reset worklists.
// ---------------------------------------------------------------------------
__global__ void vq_prep_cb(const float* __restrict__ cb) {
    if (blockIdx.x == 0 && blockIdx.y == 0 && threadIdx.x == 0 && threadIdx.y == 0) {
        g_wlc_count = 0;
        g_wlf_count = 0;
    }
    __shared__ float tile[32][33];
    const int kBase = blockIdx.x * 32;
    const int dBase = blockIdx.y * 32;
    const int tx = threadIdx.x, ty = threadIdx.y;
#pragma unroll
    for (int i = 0; i < 4; i++)
        tile[ty + i * 8][tx] = cb[(size_t)(dBase + ty + i * 8) * KCB + (kBase + tx)];
    __syncthreads();
#pragma unroll
    for (int i = 0; i < 4; i++) {
        const float v = tile[tx][ty + i * 8];
        const size_t o = (size_t)(kBase + ty + i * 8) * DIM + (dBase + tx);
        g_cbT[o] = v;
        g_cbh[o] = __float2bfloat16(v);
    }
}

// ---------------------------------------------------------------------------
// Prep 2: z -> bf16.
// ---------------------------------------------------------------------------
__global__ void vq_prep_z(const float* __restrict__ z) {
    const size_t total4 = (size_t)N_ROWS * DIM / 4;
    const size_t stride = (size_t)gridDim.x * blockDim.x;
    const float4* z4 = (const float4*)z;
    __nv_bfloat162* h2 = (__nv_bfloat162*)g_zh;
    for (size_t t = (size_t)blockIdx.x * blockDim.x + threadIdx.x; t < total4; t += stride) {
        const float4 v = z4[t];
        h2[t * 2 + 0] = __nv_bfloat162(__float2bfloat16(v.x), __float2bfloat16(v.y));
        h2[t * 2 + 1] = __nv_bfloat162(__float2bfloat16(v.z), __float2bfloat16(v.w));
    }
}

// ---------------------------------------------------------------------------
// hmma1: single-pass bf16 GEMM; epilogue = fp16 store + register row-min track.
// ---------------------------------------------------------------------------
__global__ __launch_bounds__(GEMM_THREADS, 2)
void vq_hmma1_kernel() {
    extern __shared__ char smem[];
    const uint32_t sb = smem_to_u32(smem);
    const int tid  = threadIdx.x;
    const int lane = tid & 31;
    const int wid  = tid >> 5;
    const int wm   = wid >> 2;
    const int wn   = wid & 3;
    const int t4   = lane >> 2;
    const int tq   = lane & 3;
    const int rowBase = blockIdx.x * BM;

    auto load_chunk = [&](int C) {
        const int nt = C >> 4, c = C & 15, s = C & 1;
        const uint32_t stage = sb + s * H1_STAGE;
        const int koff = c * KC;
        const int ntBase = nt * BN;
#pragma unroll
        for (int i = 0; i < 4; i++) {
            const int sg = tid + i * 256;
            const int row = sg >> 3, sc = sg & 7;
            const uint32_t so = SWZ128(row * 128 + sc * 16);
            CP_ASYNC16(stage + H1_A + so, g_zh + (size_t)(rowBase + row) * DIM + koff + sc * 8);
            CP_ASYNC16(stage + H1_B + so, g_cbh + (size_t)(ntBase + row) * DIM + koff + sc * 8);
        }
        CP_COMMIT();
    };

    float acc[4][4][4];
    float minR[8];                       // running min per owned (mi, half) row slice
#pragma unroll
    for (int j = 0; j < 8; j++) minR[j] = FLT_MAX;

    const int am  = lane >> 3;
    const int ar  = lane & 7;
    const int aRow = ((am & 1) << 3) + ar;
    const int aColB = (am >> 1) << 4;
    const int bRow = ((am >> 1) << 3) + ar;
    const int bColB = (am & 1) << 4;

    load_chunk(0);
    load_chunk(1);

    for (int C = 0; C < TOTAL_CHUNKS; C++) {
        const int s = C & 1, nt = C >> 4, c = C & 15;
        if (C < TOTAL_CHUNKS - 1) { CP_WAIT1(); } else { CP_WAIT0(); }
        __syncthreads();

        if (c == 0) {
#pragma unroll
            for (int mi = 0; mi < 4; mi++)
#pragma unroll
                for (int ni = 0; ni < 4; ni++)
#pragma unroll
                    for (int r = 0; r < 4; r++) acc[mi][ni][r] = 0.0f;
        }

        const uint32_t aB = sb + s * H1_STAGE + H1_A;
        const uint32_t bB = sb + s * H1_STAGE + H1_B;

#pragma unroll
        for (int ks = 0; ks < 4; ks++) {
            const int kb = ks * 32;
            uint32_t af[16], bf[16];
#pragma unroll
            for (int mi = 0; mi < 4; mi++) {
                const int row = wm * 64 + mi * 16 + aRow;
                LDMATRIX_X4(af[mi*4+0], af[mi*4+1], af[mi*4+2], af[mi*4+3],
                            aB + SWZ128(row * 128 + kb + aColB));
            }
#pragma unroll
            for (int np = 0; np < 2; np++) {
                const int nrow = wn * 32 + np * 16 + bRow;
                LDMATRIX_X4(bf[np*8+0], bf[np*8+1], bf[np*8+4], bf[np*8+5],
                            bB + SWZ128(nrow * 128 + kb + bColB));
            }
#pragma unroll
            for (int mi = 0; mi < 4; mi++)
#pragma unroll
                for (int ni = 0; ni < 4; ni++)
                    MMA_BF16(acc[mi][ni][0], acc[mi][ni][1], acc[mi][ni][2], acc[mi][ni][3],
                             af[mi*4+0], af[mi*4+1], af[mi*4+2], af[mi*4+3],
                             bf[ni*4+0], bf[ni*4+1]);
        }
        __syncthreads();

        if (C + 2 < TOTAL_CHUNKS) load_chunk(C + 2);

        // ---- epilogue: dump D tile as fp16 + fold into register row-min ----
        if (c == 15) {
            const int colBase = nt * BN + wn * 32 + tq * 2;
#pragma unroll
            for (int mi = 0; mi < 4; mi++) {
#pragma unroll
                for (int half = 0; half < 2; half++) {
                    const int row = rowBase + wm * 64 + mi * 16 + half * 8 + t4;
                    __half2* dst = (__half2*)(g_dots + (size_t)row * KCB);
                    float m = FLT_MAX;
#pragma unroll
                    for (int ni = 0; ni < 4; ni++) {
                        const float a0 = acc[mi][ni][half * 2 + 0];
                        const float a1 = acc[mi][ni][half * 2 + 1];
                        const int col = colBase + ni * 8;
                        dst[col >> 1] = __floats2half2_rn(a0, a1);
                        m = fminf(m, fminf(a0, a1));
                    }
                    minR[mi * 2 + half] = fminf(minR[mi * 2 + half], m);
                }
            }
        }
    }

    // ---- final row-min reduce (once): quad shuffle + smem across wn ----
    float* sMin = (float*)(smem + H1_MIN);
#pragma unroll
    for (int j = 0; j < 8; j++) {
#pragma unroll
        for (int off = 1; off <= 2; off <<= 1)
            minR[j] = fminf(minR[j], __shfl_xor_sync(0xFFFFFFFFu, minR[j], off));
    }
    if (tq == 0) {
#pragma unroll
        for (int mi = 0; mi < 4; mi++)
#pragma unroll
            for (int half = 0; half < 2; half++) {
                const int row = wm * 64 + mi * 16 + half * 8 + t4;
                sMin[row * 4 + wn] = minR[mi * 2 + half];
            }
    }
    __syncthreads();
    if (tid < BM) {
        const float m = fminf(fminf(sMin[tid * 4 + 0], sMin[tid * 4 + 1]),
                              fminf(sMin[tid * 4 + 2], sMin[tid * 4 + 3]));
        g_rowmin[rowBase + tid] = m;
    }
}

// ---------------------------------------------------------------------------
// scan: warp per row, SINGLE pass over ROW_U4 = 1024 uint4 groups.
// thr = g_rowmin[row] + WINDOW; min8-vs-thr per 16B; unpack only on rare hit.
// count==1 -> argmin directly; 2..8 -> wlc; >8 -> wlf.
// ---------------------------------------------------------------------------
__global__ __launch_bounds__(256)
void vq_scan_kernel() {
    __shared__ int scnt[8];
    const int w    = threadIdx.x >> 5;
    const int lane = threadIdx.x & 31;
    const int row  = blockIdx.x * 8 + w;
    const uint4* dp = (const uint4*)(g_dots + (size_t)row * KCB);

    if (lane == 0) scnt[w] = 0;
    __syncwarp();

    const float thr = g_rowmin[row] + WINDOW;
#pragma unroll 4
    for (int i = lane; i < ROW_U4; i += 32) {
        const uint4 u = dp[i];
        const __half2 h0 = *(const __half2*)&u.x;
        const __half2 h1 = *(const __half2*)&u.y;
        const __half2 h2 = *(const __half2*)&u.z;
        const __half2 h3 = *(const __half2*)&u.w;
        const __half2 g2 = __hmin2(__hmin2(h0, h1), __hmin2(h2, h3));
        const float g = fminf(__low2float(g2), __high2float(g2));
        if (g < thr) {
            const __half2 hs[4] = { h0, h1, h2, h3 };
#pragma unroll
            for (int q = 0; q < 4; q++) {
                const float v0 = __low2float(hs[q]), v1 = __high2float(hs[q]);
                if (v0 < thr) {
                    const int p = atomicAdd(&scnt[w], 1);
                    if (p < CAND_CAP) g_cand[(size_t)row * CAND_CAP + p] = i * 8 + q * 2;
                }
                if (v1 < thr) {
                    const int p = atomicAdd(&scnt[w], 1);
                    if (p < CAND_CAP) g_cand[(size_t)row * CAND_CAP + p] = i * 8 + q * 2 + 1;
                }
            }
        }
    }
    __syncwarp();

    if (lane == 0) {
        const int total = scnt[w];
        g_ccnt[row] = total;
        if (total > CAND_CAP) {
            const int p = atomicAdd(&g_wlf_count, 1);
            if (p < WLF_CAP) g_wlf[p] = row;
        } else if (total >= 2) {
            const int p = atomicAdd(&g_wlc_count, 1);
            if (p < WLC_CAP) g_wlc[p] = row;
        } else {
            g_argmin[row] = g_cand[(size_t)row * CAND_CAP];  // sole candidate
        }
    }
}

// ---------------------------------------------------------------------------
// refine_cand: exact fp64 rescore of tracked candidates. One warp per row.
// ---------------------------------------------------------------------------
__global__ __launch_bounds__(256)
void vq_refine_cand(const float* __restrict__ z) {
    const int cnt  = min(g_wlc_count, WLC_CAP);
    const int lane = threadIdx.x & 31;
    const int wrp  = threadIdx.x >> 5;

    for (int wi = blockIdx.x * 8 + wrp; wi < cnt; wi += gridDim.x * 8) {
        const int row = g_wlc[wi];
        const int nc = min(g_ccnt[row], CAND_CAP);
        const float* zr = z + (size_t)row * DIM;

        double bestV = 1e300;
        int    bestI = 0x7FFFFFFF;
        for (int j = 0; j < nc; j++) {
            const int k = g_cand[(size_t)row * CAND_CAP + j];
            const float* cw = g_cbT + (size_t)k * DIM;
            double sd = 0.0;
#pragma unroll 4
            for (int d = lane; d < DIM; d += 32)
                sd += (double)cw[d] * (double)zr[d];
#pragma unroll
            for (int off = 16; off > 0; off >>= 1)
                sd += __shfl_down_sync(0xFFFFFFFFu, sd, off);
            sd = __shfl_sync(0xFFFFFFFFu, sd, 0);
            if (sd < bestV || (sd == bestV && k < bestI)) { bestV = sd; bestI = k; }
        }
        if (lane == 0) g_argmin[row] = bestI;
    }
}

// ---------------------------------------------------------------------------
// refine_full: exact pass (fp32 full rescan -> fp64 finish) for overflow rows.
// ---------------------------------------------------------------------------
__global__ __launch_bounds__(256)
void vq_refine_full(const float* __restrict__ A) {
    __shared__ float  zs[DIM];
    __shared__ float  dots[KCB];
    __shared__ float  red[256];
    __shared__ int    cands[MAX_CAND];
    __shared__ double cval[MAX_CAND];
    __shared__ int    ncand;

    const int tid  = threadIdx.x;
    const int lane = tid & 31;
    const int wrp  = tid >> 5;
    const int cnt  = min(g_wlf_count, WLF_CAP);

    for (int wi = blockIdx.x; wi < cnt; wi += gridDim.x) {
        const int row = g_wlf[wi];
#pragma unroll
        for (int i = 0; i < DIM / 256; i++)
            zs[tid + i * 256] = A[(size_t)row * DIM + tid + i * 256];
        if (tid == 0) ncand = 0;
        __syncthreads();

        const float4* z4 = (const float4*)zs;
        float localMin = FLT_MAX;
        for (int k = tid; k < KCB; k += 256) {
            const float4* c4 = (const float4*)(g_cbT + (size_t)k * DIM);
            float sacc = 0.0f;
#pragma unroll 8
            for (int d = 0; d < DIM / 4; d++) {
                const float4 cc = c4[d];
                const float4 zz = z4[d];
                sacc = fmaf(cc.x, zz.x, sacc);
                sacc = fmaf(cc.y, zz.y, sacc);
                sacc = fmaf(cc.z, zz.z, sacc);
                sacc = fmaf(cc.w, zz.w, sacc);
            }
            dots[k] = sacc;
            localMin = fminf(localMin, sacc);
        }
        red[tid] = localMin;
        __syncthreads();
        for (int off = 128; off > 0; off >>= 1) {
            if (tid < off) red[tid] = fminf(red[tid], red[tid + off]);
            __syncthreads();
        }
        const float bmin = red[0];

        for (int k = tid; k < KCB; k += 256) {
            if (dots[k] < bmin + TAU3) {
                const int p = atomicAdd(&ncand, 1);
                if (p < MAX_CAND) cands[p] = k;
            }
        }
        __syncthreads();
        const int nc = min(ncand, MAX_CAND);

        for (int ci = wrp; ci < nc; ci += 8) {
            const int k = cands[ci];
            const float* cbp = g_cbT + (size_t)k * DIM;
            double sd = 0.0;
            for (int d = lane; d < DIM; d += 32)
                sd += (double)cbp[d] * (double)zs[d];
#pragma unroll
            for (int off = 16; off > 0; off >>= 1)
                sd += __shfl_down_sync(0xFFFFFFFFu, sd, off);
            if (lane == 0) cval[ci] = sd;
        }
        __syncthreads();

        if (tid == 0) {
            double bv = cval[0];
            int    bi = cands[0];
            for (int c2 = 1; c2 < nc; c2++) {
                const double v = cval[c2];
                const int    x = cands[c2];
                if (v < bv || (v == bv && x < bi)) { bv = v; bi = x; }
            }
            g_argmin[row] = bi;
        }
        __syncthreads();
    }
}

// ---------------------------------------------------------------------------
// Gather: out[n][:] = g_cbT[argmin[n]][:]
// ---------------------------------------------------------------------------
__global__ void vq_gather_kernel(float* __restrict__ out) {
    const int n = blockIdx.x;
    const int idx = g_argmin[n];
    const float4* src = (const float4*)(g_cbT + (size_t)idx * DIM);
    float4* dst = (float4*)(out + (size_t)n * DIM);
    dst[threadIdx.x] = src[threadIdx.x];
}

// ---------------------------------------------------------------------------
extern "C" void kernel_launch(void* const* d_in, const int* in_sizes, int n_in,
                              void* d_out, int out_size) {
    const float* z  = (const float*)d_in[0];
    const float* cb = (const float*)d_in[1];
    float* out = (float*)d_out;

    cudaFuncSetAttribute(vq_hmma1_kernel, cudaFuncAttributeMaxDynamicSharedMemorySize, H1_SMEM);

    dim3 tgrid(KCB / 32, DIM / 32);
    dim3 tblk(32, 8);
    vq_prep_cb<<<tgrid, tblk>>>(cb);
    vq_prep_z<<<8192, 256>>>(z);

    vq_hmma1_kernel<<<N_ROWS / BM, GEMM_THREADS, H1_SMEM>>>();

    vq_scan_kernel<<<N_ROWS / 8, 256>>>();
    vq_refine_cand<<<2048, 256>>>(z);
    vq_refine_full<<<64, 256>>>(z);
    vq_gather_kernel<<<N_ROWS, 256>>>(out);
}

// round 16
// speedup vs baseline: 1.0502x; 1.0502x over previous
#include <cuda_runtime.h>
#include <cuda_bf16.h>
#include <cuda_fp16.h>
#include <cstdint>
#include <cfloat>

#define N_ROWS 65536
#define DIM    1024
#define KCB    8192

#define WINDOW   0.40f     // candidate window (fp16 store err + bf16 GEMM noise, >2x margin)
#define TAU3     2.0e-3f   // full-refine fp32->fp64 shortlist window
#define WLC_CAP  32768
#define WLF_CAP  1024
#define CAND_CAP 8
#define MAX_CAND 64

#define BM 128
#define BN 128
#define KC 64
#define N_TILES (KCB / BN)                        // 64
#define CHUNKS_PER_TILE (DIM / KC)                // 16
#define TOTAL_CHUNKS (N_TILES * CHUNKS_PER_TILE)  // 1024
#define GEMM_THREADS 256

// row = 8192 halves = 16384 bytes = 1024 x uint4; 32 groups per lane
#define ROW_U4 1024
#define GRP_PER_LANE 32

// ---- hmma1 SMEM: 2 stages only (R14 shape — do not touch) ----
#define H1_STAGE   32768
#define H1_A       0
#define H1_B       16384
#define H1_SMEM    (2 * H1_STAGE)                 // 65536

// ---- scratch (__device__ globals; allocation-free rule) ----
__device__ __nv_bfloat16 g_zh[(size_t)N_ROWS * DIM];   // 128 MB
__device__ __nv_bfloat16 g_cbh[(size_t)KCB * DIM];     // 16 MB
__device__ float         g_cbT[(size_t)KCB * DIM];     // 32 MB
__device__ __half        g_dots[(size_t)N_ROWS * KCB]; // 1 GB dot matrix (fp16)
__device__ int   g_cand[(size_t)N_ROWS * CAND_CAP];    // per-row candidates
__device__ int   g_ccnt[N_ROWS];
__device__ int   g_argmin[N_ROWS];
__device__ int   g_wlc[WLC_CAP];
__device__ int   g_wlc_count;
__device__ int   g_wlf[WLF_CAP];
__device__ int   g_wlf_count;

// ============================ helpers ============================
__device__ __forceinline__ uint32_t smem_to_u32(const void* p) {
    uint32_t a;
    asm("{ .reg .u64 t; cvta.to.shared.u64 t, %1; cvt.u32.u64 %0, t; }" : "=r"(a) : "l"(p));
    return a;
}
#define SWZ128(o) ((o) ^ (((o) >> 3) & 0x70))

#define CP_ASYNC16(sm, g) \
    asm volatile("cp.async.cg.shared.global [%0], [%1], 16;" :: "r"(sm), "l"(g) : "memory")
#define CP_COMMIT()  asm volatile("cp.async.commit_group;" ::: "memory")
#define CP_WAIT1()   asm volatile("cp.async.wait_group 1;" ::: "memory")
#define CP_WAIT0()   asm volatile("cp.async.wait_group 0;" ::: "memory")

#define LDMATRIX_X4(r0, r1, r2, r3, a) \
    asm volatile("ldmatrix.sync.aligned.m8n8.x4.shared.b16 {%0,%1,%2,%3}, [%4];" \
                 : "=r"(r0), "=r"(r1), "=r"(r2), "=r"(r3) : "r"(a))

#define MMA_BF16(c0, c1, c2, c3, a0, a1, a2, a3, b0, b1) \
    asm volatile("mma.sync.aligned.m16n8k16.row.col.f32.bf16.bf16.f32 " \
                 "{%0,%1,%2,%3}, {%4,%5,%6,%7}, {%8,%9}, {%0,%1,%2,%3};" \
                 : "+f"(c0), "+f"(c1), "+f"(c2), "+f"(c3) \
                 : "r"(a0), "r"(a1), "r"(a2), "r"(a3), "r"(b0), "r"(b1))

// ---------------------------------------------------------------------------
// Prep 1: transpose codebook -> cbT fp32 + cbh bf16; reset worklists.
// ---------------------------------------------------------------------------
__global__ void vq_prep_cb(const float* __restrict__ cb) {
    if (blockIdx.x == 0 && blockIdx.y == 0 && threadIdx.x == 0 && threadIdx.y == 0) {
        g_wlc_count = 0;
        g_wlf_count = 0;
    }
    __shared__ float tile[32][33];
    const int kBase = blockIdx.x * 32;
    const int dBase = blockIdx.y * 32;
    const int tx = threadIdx.x, ty = threadIdx.y;
#pragma unroll
    for (int i = 0; i < 4; i++)
        tile[ty + i * 8][tx] = cb[(size_t)(dBase + ty + i * 8) * KCB + (kBase + tx)];
    __syncthreads();
#pragma unroll
    for (int i = 0; i < 4; i++) {
        const float v = tile[tx][ty + i * 8];
        const size_t o = (size_t)(kBase + ty + i * 8) * DIM + (dBase + tx);
        g_cbT[o] = v;
        g_cbh[o] = __float2bfloat16(v);
    }
}

// ---------------------------------------------------------------------------
// Prep 2: z -> bf16.
// ---------------------------------------------------------------------------
__global__ void vq_prep_z(const float* __restrict__ z) {
    const size_t total4 = (size_t)N_ROWS * DIM / 4;
    const size_t stride = (size_t)gridDim.x * blockDim.x;
    const float4* z4 = (const float4*)z;
    __nv_bfloat162* h2 = (__nv_bfloat162*)g_zh;
    for (size_t t = (size_t)blockIdx.x * blockDim.x + threadIdx.x; t < total4; t += stride) {
        const float4 v = z4[t];
        h2[t * 2 + 0] = __nv_bfloat162(__float2bfloat16(v.x), __float2bfloat16(v.y));
        h2[t * 2 + 1] = __nv_bfloat162(__float2bfloat16(v.z), __float2bfloat16(v.w));
    }
}

// ---------------------------------------------------------------------------
// hmma1: single-pass bf16 GEMM; epilogue = store D tile as fp16 (R14 verbatim).
// ---------------------------------------------------------------------------
__global__ __launch_bounds__(GEMM_THREADS, 2)
void vq_hmma1_kernel() {
    extern __shared__ char smem[];
    const uint32_t sb = smem_to_u32(smem);
    const int tid  = threadIdx.x;
    const int lane = tid & 31;
    const int wid  = tid >> 5;
    const int wm   = wid >> 2;
    const int wn   = wid & 3;
    const int t4   = lane >> 2;
    const int tq   = lane & 3;
    const int rowBase = blockIdx.x * BM;

    auto load_chunk = [&](int C) {
        const int nt = C >> 4, c = C & 15, s = C & 1;
        const uint32_t stage = sb + s * H1_STAGE;
        const int koff = c * KC;
        const int ntBase = nt * BN;
#pragma unroll
        for (int i = 0; i < 4; i++) {
            const int sg = tid + i * 256;
            const int row = sg >> 3, sc = sg & 7;
            const uint32_t so = SWZ128(row * 128 + sc * 16);
            CP_ASYNC16(stage + H1_A + so, g_zh + (size_t)(rowBase + row) * DIM + koff + sc * 8);
            CP_ASYNC16(stage + H1_B + so, g_cbh + (size_t)(ntBase + row) * DIM + koff + sc * 8);
        }
        CP_COMMIT();
    };

    float acc[4][4][4];

    const int am  = lane >> 3;
    const int ar  = lane & 7;
    const int aRow = ((am & 1) << 3) + ar;
    const int aColB = (am >> 1) << 4;
    const int bRow = ((am >> 1) << 3) + ar;
    const int bColB = (am & 1) << 4;

    load_chunk(0);
    load_chunk(1);

    for (int C = 0; C < TOTAL_CHUNKS; C++) {
        const int s = C & 1, nt = C >> 4, c = C & 15;
        if (C < TOTAL_CHUNKS - 1) { CP_WAIT1(); } else { CP_WAIT0(); }
        __syncthreads();

        if (c == 0) {
#pragma unroll
            for (int mi = 0; mi < 4; mi++)
#pragma unroll
                for (int ni = 0; ni < 4; ni++)
#pragma unroll
                    for (int r = 0; r < 4; r++) acc[mi][ni][r] = 0.0f;
        }

        const uint32_t aB = sb + s * H1_STAGE + H1_A;
        const uint32_t bB = sb + s * H1_STAGE + H1_B;

#pragma unroll
        for (int ks = 0; ks < 4; ks++) {
            const int kb = ks * 32;
            uint32_t af[16], bf[16];
#pragma unroll
            for (int mi = 0; mi < 4; mi++) {
                const int row = wm * 64 + mi * 16 + aRow;
                LDMATRIX_X4(af[mi*4+0], af[mi*4+1], af[mi*4+2], af[mi*4+3],
                            aB + SWZ128(row * 128 + kb + aColB));
            }
#pragma unroll
            for (int np = 0; np < 2; np++) {
                const int nrow = wn * 32 + np * 16 + bRow;
                LDMATRIX_X4(bf[np*8+0], bf[np*8+1], bf[np*8+4], bf[np*8+5],
                            bB + SWZ128(nrow * 128 + kb + bColB));
            }
#pragma unroll
            for (int mi = 0; mi < 4; mi++)
#pragma unroll
                for (int ni = 0; ni < 4; ni++)
                    MMA_BF16(acc[mi][ni][0], acc[mi][ni][1], acc[mi][ni][2], acc[mi][ni][3],
                             af[mi*4+0], af[mi*4+1], af[mi*4+2], af[mi*4+3],
                             bf[ni*4+0], bf[ni*4+1]);
        }
        __syncthreads();

        if (C + 2 < TOTAL_CHUNKS) load_chunk(C + 2);

        // ---- epilogue: dump D tile as fp16 ----
        if (c == 15) {
            const int colBase = nt * BN + wn * 32 + tq * 2;
#pragma unroll
            for (int mi = 0; mi < 4; mi++) {
#pragma unroll
                for (int half = 0; half < 2; half++) {
                    const int row = rowBase + wm * 64 + mi * 16 + half * 8 + t4;
                    __half2* dst = (__half2*)(g_dots + (size_t)row * KCB);
#pragma unroll
                    for (int ni = 0; ni < 4; ni++) {
                        const int col = colBase + ni * 8;
                        dst[col >> 1] = __floats2half2_rn(acc[mi][ni][half * 2 + 0],
                                                          acc[mi][ni][half * 2 + 1]);
                    }
                }
            }
        }
    }
}

// ---------------------------------------------------------------------------
// scan: warp per row, single DRAM read.
// Pass A: stream 32 groups/lane; keep per-group min8 in registers + running min.
// Pass B: register sweep; re-fetch (L2-hit) only groups with g[j] < thr.
// count==1 -> argmin directly; 2..8 -> wlc; >8 -> wlf.
// ---------------------------------------------------------------------------
__global__ __launch_bounds__(256)
void vq_scan_kernel() {
    __shared__ int scnt[8];
    const int w    = threadIdx.x >> 5;
    const int lane = threadIdx.x & 31;
    const int row  = blockIdx.x * 8 + w;
    const uint4* dp = (const uint4*)(g_dots + (size_t)row * KCB);

    // ---- pass A: stream + per-group min8 in registers ----
    float g[GRP_PER_LANE];
    __half2 m2 = __float2half2_rn(6.0e4f);
#pragma unroll
    for (int j = 0; j < GRP_PER_LANE; j++) {
        const uint4 u = dp[lane + j * 32];
        const __half2 h0 = *(const __half2*)&u.x;
        const __half2 h1 = *(const __half2*)&u.y;
        const __half2 h2 = *(const __half2*)&u.z;
        const __half2 h3 = *(const __half2*)&u.w;
        const __half2 g2 = __hmin2(__hmin2(h0, h1), __hmin2(h2, h3));
        g[j] = fminf(__low2float(g2), __high2float(g2));
        m2 = __hmin2(m2, g2);
    }
    float minv = fminf(__low2float(m2), __high2float(m2));
#pragma unroll
    for (int off = 16; off > 0; off >>= 1)
        minv = fminf(minv, __shfl_xor_sync(0xFFFFFFFFu, minv, off));

    if (lane == 0) scnt[w] = 0;
    __syncwarp();

    // ---- pass B: register sweep; rare re-fetch + unpack ----
    const float thr = minv + WINDOW;
#pragma unroll
    for (int j = 0; j < GRP_PER_LANE; j++) {
        if (g[j] < thr) {
            const int gi = lane + j * 32;
            const uint4 u = dp[gi];
            const __half2 hs[4] = { *(const __half2*)&u.x, *(const __half2*)&u.y,
                                    *(const __half2*)&u.z, *(const __half2*)&u.w };
#pragma unroll
            for (int q = 0; q < 4; q++) {
                const float v0 = __low2float(hs[q]), v1 = __high2float(hs[q]);
                if (v0 < thr) {
                    const int p = atomicAdd(&scnt[w], 1);
                    if (p < CAND_CAP) g_cand[(size_t)row * CAND_CAP + p] = gi * 8 + q * 2;
                }
                if (v1 < thr) {
                    const int p = atomicAdd(&scnt[w], 1);
                    if (p < CAND_CAP) g_cand[(size_t)row * CAND_CAP + p] = gi * 8 + q * 2 + 1;
                }
            }
        }
    }
    __syncwarp();

    if (lane == 0) {
        const int total = scnt[w];
        g_ccnt[row] = total;
        if (total > CAND_CAP) {
            const int p = atomicAdd(&g_wlf_count, 1);
            if (p < WLF_CAP) g_wlf[p] = row;
        } else if (total >= 2) {
            const int p = atomicAdd(&g_wlc_count, 1);
            if (p < WLC_CAP) g_wlc[p] = row;
        } else {
            g_argmin[row] = g_cand[(size_t)row * CAND_CAP];  // sole candidate
        }
    }
}

// ---------------------------------------------------------------------------
// refine_cand: exact fp64 rescore of tracked candidates. One warp per row.
// ---------------------------------------------------------------------------
__global__ __launch_bounds__(256)
void vq_refine_cand(const float* __restrict__ z) {
    const int cnt  = min(g_wlc_count, WLC_CAP);
    const int lane = threadIdx.x & 31;
    const int wrp  = threadIdx.x >> 5;

    for (int wi = blockIdx.x * 8 + wrp; wi < cnt; wi += gridDim.x * 8) {
        const int row = g_wlc[wi];
        const int nc = min(g_ccnt[row], CAND_CAP);
        const float* zr = z + (size_t)row * DIM;

        double bestV = 1e300;
        int    bestI = 0x7FFFFFFF;
        for (int j = 0; j < nc; j++) {
            const int k = g_cand[(size_t)row * CAND_CAP + j];
            const float* cw = g_cbT + (size_t)k * DIM;
            double sd = 0.0;
#pragma unroll 4
            for (int d = lane; d < DIM; d += 32)
                sd += (double)cw[d] * (double)zr[d];
#pragma unroll
            for (int off = 16; off > 0; off >>= 1)
                sd += __shfl_down_sync(0xFFFFFFFFu, sd, off);
            sd = __shfl_sync(0xFFFFFFFFu, sd, 0);
            if (sd < bestV || (sd == bestV && k < bestI)) { bestV = sd; bestI = k; }
        }
        if (lane == 0) g_argmin[row] = bestI;
    }
}

// ---------------------------------------------------------------------------
// refine_full: exact pass (fp32 full rescan -> fp64 finish) for overflow rows.
// ---------------------------------------------------------------------------
__global__ __launch_bounds__(256)
void vq_refine_full(const float* __restrict__ A) {
    __shared__ float  zs[DIM];
    __shared__ float  dots[KCB];
    __shared__ float  red[256];
    __shared__ int    cands[MAX_CAND];
    __shared__ double cval[MAX_CAND];
    __shared__ int    ncand;

    const int tid  = threadIdx.x;
    const int lane = tid & 31;
    const int wrp  = tid >> 5;
    const int cnt  = min(g_wlf_count, WLF_CAP);

    for (int wi = blockIdx.x; wi < cnt; wi += gridDim.x) {
        const int row = g_wlf[wi];
#pragma unroll
        for (int i = 0; i < DIM / 256; i++)
            zs[tid + i * 256] = A[(size_t)row * DIM + tid + i * 256];
        if (tid == 0) ncand = 0;
        __syncthreads();

        const float4* z4 = (const float4*)zs;
        float localMin = FLT_MAX;
        for (int k = tid; k < KCB; k += 256) {
            const float4* c4 = (const float4*)(g_cbT + (size_t)k * DIM);
            float sacc = 0.0f;
#pragma unroll 8
            for (int d = 0; d < DIM / 4; d++) {
                const float4 cc = c4[d];
                const float4 zz = z4[d];
                sacc = fmaf(cc.x, zz.x, sacc);
                sacc = fmaf(cc.y, zz.y, sacc);
                sacc = fmaf(cc.z, zz.z, sacc);
                sacc = fmaf(cc.w, zz.w, sacc);
            }
            dots[k] = sacc;
            localMin = fminf(localMin, sacc);
        }
        red[tid] = localMin;
        __syncthreads();
        for (int off = 128; off > 0; off >>= 1) {
            if (tid < off) red[tid] = fminf(red[tid], red[tid + off]);
            __syncthreads();
        }
        const float bmin = red[0];

        for (int k = tid; k < KCB; k += 256) {
            if (dots[k] < bmin + TAU3) {
                const int p = atomicAdd(&ncand, 1);
                if (p < MAX_CAND) cands[p] = k;
            }
        }
        __syncthreads();
        const int nc = min(ncand, MAX_CAND);

        for (int ci = wrp; ci < nc; ci += 8) {
            const int k = cands[ci];
            const float* cbp = g_cbT + (size_t)k * DIM;
            double sd = 0.0;
            for (int d = lane; d < DIM; d += 32)
                sd += (double)cbp[d] * (double)zs[d];
#pragma unroll
            for (int off = 16; off > 0; off >>= 1)
                sd += __shfl_down_sync(0xFFFFFFFFu, sd, off);
            if (lane == 0) cval[ci] = sd;
        }
        __syncthreads();

        if (tid == 0) {
            double bv = cval[0];
            int    bi = cands[0];
            for (int c2 = 1; c2 < nc; c2++) {
                const double v = cval[c2];
                const int    x = cands[c2];
                if (v < bv || (v == bv && x < bi)) { bv = v; bi = x; }
            }
            g_argmin[row] = bi;
        }
        __syncthreads();
    }
}

// ---------------------------------------------------------------------------
// Gather: out[n][:] = g_cbT[argmin[n]][:]
// ---------------------------------------------------------------------------
__global__ void vq_gather_kernel(float* __restrict__ out) {
    const int n = blockIdx.x;
    const int idx = g_argmin[n];
    const float4* src = (const float4*)(g_cbT + (size_t)idx * DIM);
    float4* dst = (float4*)(out + (size_t)n * DIM);
    dst[threadIdx.x] = src[threadIdx.x];
}

// ---------------------------------------------------------------------------
extern "C" void kernel_launch(void* const* d_in, const int* in_sizes, int n_in,
                              void* d_out, int out_size) {
    const float* z  = (const float*)d_in[0];
    const float* cb = (const float*)d_in[1];
    float* out = (float*)d_out;

    cudaFuncSetAttribute(vq_hmma1_kernel, cudaFuncAttributeMaxDynamicSharedMemorySize, H1_SMEM);

    dim3 tgrid(KCB / 32, DIM / 32);
    dim3 tblk(32, 8);
    vq_prep_cb<<<tgrid, tblk>>>(cb);
    vq_prep_z<<<8192, 256>>>(z);

    vq_hmma1_kernel<<<N_ROWS / BM, GEMM_THREADS, H1_SMEM>>>();

    vq_scan_kernel<<<N_ROWS / 8, 256>>>();
    vq_refine_cand<<<2048, 256>>>(z);
    vq_refine_full<<<64, 256>>>(z);
    vq_gather_kernel<<<N_ROWS, 256>>>(out);
}

// round 17
// speedup vs baseline: 1.0646x; 1.0137x over previous
#include <cuda_runtime.h>
#include <cuda_bf16.h>
#include <cuda_fp16.h>
#include <cstdint>
#include <cfloat>

#define N_ROWS 65536
#define DIM    1024
#define KCB    8192

#define WINDOW   0.40f     // candidate window (fp16 store err + bf16 GEMM noise, >2x margin)
#define TAU3     2.0e-3f   // full-refine fp32->fp64 shortlist window
#define WLC_CAP  32768
#define WLF_CAP  1024
#define CAND_CAP 8
#define MAX_CAND 64

#define BM 128
#define BN 128
#define KC 64
#define N_TILES (KCB / BN)                        // 64
#define CHUNKS_PER_TILE (DIM / KC)                // 16
#define TOTAL_CHUNKS (N_TILES * CHUNKS_PER_TILE)  // 1024
#define GEMM_THREADS 256

// row = 8192 halves = 16384 bytes = 1024 x uint4; 32 groups per lane
#define ROW_U4 1024
#define GRP_PER_LANE 32

// ---- hmma1 SMEM: 2 stages only (R14 shape — do not touch) ----
#define H1_STAGE   32768
#define H1_A       0
#define H1_B       16384
#define H1_SMEM    (2 * H1_STAGE)                 // 65536

// ---- scratch (__device__ globals; allocation-free rule) ----
__device__ __nv_bfloat16 g_zh[(size_t)N_ROWS * DIM];   // 128 MB
__device__ __nv_bfloat16 g_cbh[(size_t)KCB * DIM];     // 16 MB
__device__ float         g_cbT[(size_t)KCB * DIM];     // 32 MB
__device__ __half        g_dots[(size_t)N_ROWS * KCB]; // 1 GB dot matrix (fp16)
__device__ int   g_cand[(size_t)N_ROWS * CAND_CAP];    // per-row candidates
__device__ int   g_ccnt[N_ROWS];
__device__ int   g_argmin[N_ROWS];
__device__ int   g_wlc[WLC_CAP];
__device__ int   g_wlc_count;
__device__ int   g_wlf[WLF_CAP];
__device__ int   g_wlf_count;

// ============================ helpers ============================
__device__ __forceinline__ uint32_t smem_to_u32(const void* p) {
    uint32_t a;
    asm("{ .reg .u64 t; cvta.to.shared.u64 t, %1; cvt.u32.u64 %0, t; }" : "=r"(a) : "l"(p));
    return a;
}
#define SWZ128(o) ((o) ^ (((o) >> 3) & 0x70))

#define CP_ASYNC16(sm, g) \
    asm volatile("cp.async.cg.shared.global [%0], [%1], 16;" :: "r"(sm), "l"(g) : "memory")
#define CP_COMMIT()  asm volatile("cp.async.commit_group;" ::: "memory")
#define CP_WAIT1()   asm volatile("cp.async.wait_group 1;" ::: "memory")
#define CP_WAIT0()   asm volatile("cp.async.wait_group 0;" ::: "memory")

#define LDMATRIX_X4(r0, r1, r2, r3, a) \
    asm volatile("ldmatrix.sync.aligned.m8n8.x4.shared.b16 {%0,%1,%2,%3}, [%4];" \
                 : "=r"(r0), "=r"(r1), "=r"(r2), "=r"(r3) : "r"(a))

#define MMA_BF16(c0, c1, c2, c3, a0, a1, a2, a3, b0, b1) \
    asm volatile("mma.sync.aligned.m16n8k16.row.col.f32.bf16.bf16.f32 " \
                 "{%0,%1,%2,%3}, {%4,%5,%6,%7}, {%8,%9}, {%0,%1,%2,%3};" \
                 : "+f"(c0), "+f"(c1), "+f"(c2), "+f"(c3) \
                 : "r"(a0), "r"(a1), "r"(a2), "r"(a3), "r"(b0), "r"(b1))

// ---------------------------------------------------------------------------
// Prep 1: transpose codebook -> cbT fp32 + cbh bf16; reset worklists.
// ---------------------------------------------------------------------------
__global__ void vq_prep_cb(const float* __restrict__ cb) {
    if (blockIdx.x == 0 && blockIdx.y == 0 && threadIdx.x == 0 && threadIdx.y == 0) {
        g_wlc_count = 0;
        g_wlf_count = 0;
    }
    __shared__ float tile[32][33];
    const int kBase = blockIdx.x * 32;
    const int dBase = blockIdx.y * 32;
    const int tx = threadIdx.x, ty = threadIdx.y;
#pragma unroll
    for (int i = 0; i < 4; i++)
        tile[ty + i * 8][tx] = cb[(size_t)(dBase + ty + i * 8) * KCB + (kBase + tx)];
    __syncthreads();
#pragma unroll
    for (int i = 0; i < 4; i++) {
        const float v = tile[tx][ty + i * 8];
        const size_t o = (size_t)(kBase + ty + i * 8) * DIM + (dBase + tx);
        g_cbT[o] = v;
        g_cbh[o] = __float2bfloat16(v);
    }
}

// ---------------------------------------------------------------------------
// Prep 2: z -> bf16.
// ---------------------------------------------------------------------------
__global__ void vq_prep_z(const float* __restrict__ z) {
    const size_t total4 = (size_t)N_ROWS * DIM / 4;
    const size_t stride = (size_t)gridDim.x * blockDim.x;
    const float4* z4 = (const float4*)z;
    __nv_bfloat162* h2 = (__nv_bfloat162*)g_zh;
    for (size_t t = (size_t)blockIdx.x * blockDim.x + threadIdx.x; t < total4; t += stride) {
        const float4 v = z4[t];
        h2[t * 2 + 0] = __nv_bfloat162(__float2bfloat16(v.x), __float2bfloat16(v.y));
        h2[t * 2 + 1] = __nv_bfloat162(__float2bfloat16(v.z), __float2bfloat16(v.w));
    }
}

// ---------------------------------------------------------------------------
// hmma1: single-pass bf16 GEMM; epilogue = store D tile as fp16 (R14 verbatim).
// ---------------------------------------------------------------------------
__global__ __launch_bounds__(GEMM_THREADS, 2)
void vq_hmma1_kernel() {
    extern __shared__ char smem[];
    const uint32_t sb = smem_to_u32(smem);
    const int tid  = threadIdx.x;
    const int lane = tid & 31;
    const int wid  = tid >> 5;
    const int wm   = wid >> 2;
    const int wn   = wid & 3;
    const int t4   = lane >> 2;
    const int tq   = lane & 3;
    const int rowBase = blockIdx.x * BM;

    auto load_chunk = [&](int C) {
        const int nt = C >> 4, c = C & 15, s = C & 1;
        const uint32_t stage = sb + s * H1_STAGE;
        const int koff = c * KC;
        const int ntBase = nt * BN;
#pragma unroll
        for (int i = 0; i < 4; i++) {
            const int sg = tid + i * 256;
            const int row = sg >> 3, sc = sg & 7;
            const uint32_t so = SWZ128(row * 128 + sc * 16);
            CP_ASYNC16(stage + H1_A + so, g_zh + (size_t)(rowBase + row) * DIM + koff + sc * 8);
            CP_ASYNC16(stage + H1_B + so, g_cbh + (size_t)(ntBase + row) * DIM + koff + sc * 8);
        }
        CP_COMMIT();
    };

    float acc[4][4][4];

    const int am  = lane >> 3;
    const int ar  = lane & 7;
    const int aRow = ((am & 1) << 3) + ar;
    const int aColB = (am >> 1) << 4;
    const int bRow = ((am >> 1) << 3) + ar;
    const int bColB = (am & 1) << 4;

    load_chunk(0);
    load_chunk(1);

    for (int C = 0; C < TOTAL_CHUNKS; C++) {
        const int s = C & 1, nt = C >> 4, c = C & 15;
        if (C < TOTAL_CHUNKS - 1) { CP_WAIT1(); } else { CP_WAIT0(); }
        __syncthreads();

        if (c == 0) {
#pragma unroll
            for (int mi = 0; mi < 4; mi++)
#pragma unroll
                for (int ni = 0; ni < 4; ni++)
#pragma unroll
                    for (int r = 0; r < 4; r++) acc[mi][ni][r] = 0.0f;
        }

        const uint32_t aB = sb + s * H1_STAGE + H1_A;
        const uint32_t bB = sb + s * H1_STAGE + H1_B;

#pragma unroll
        for (int ks = 0; ks < 4; ks++) {
            const int kb = ks * 32;
            uint32_t af[16], bf[16];
#pragma unroll
            for (int mi = 0; mi < 4; mi++) {
                const int row = wm * 64 + mi * 16 + aRow;
                LDMATRIX_X4(af[mi*4+0], af[mi*4+1], af[mi*4+2], af[mi*4+3],
                            aB + SWZ128(row * 128 + kb + aColB));
            }
#pragma unroll
            for (int np = 0; np < 2; np++) {
                const int nrow = wn * 32 + np * 16 + bRow;
                LDMATRIX_X4(bf[np*8+0], bf[np*8+1], bf[np*8+4], bf[np*8+5],
                            bB + SWZ128(nrow * 128 + kb + bColB));
            }
#pragma unroll
            for (int mi = 0; mi < 4; mi++)
#pragma unroll
                for (int ni = 0; ni < 4; ni++)
                    MMA_BF16(acc[mi][ni][0], acc[mi][ni][1], acc[mi][ni][2], acc[mi][ni][3],
                             af[mi*4+0], af[mi*4+1], af[mi*4+2], af[mi*4+3],
                             bf[ni*4+0], bf[ni*4+1]);
        }
        __syncthreads();

        if (C + 2 < TOTAL_CHUNKS) load_chunk(C + 2);

        // ---- epilogue: dump D tile as fp16 ----
        if (c == 15) {
            const int colBase = nt * BN + wn * 32 + tq * 2;
#pragma unroll
            for (int mi = 0; mi < 4; mi++) {
#pragma unroll
                for (int half = 0; half < 2; half++) {
                    const int row = rowBase + wm * 64 + mi * 16 + half * 8 + t4;
                    __half2* dst = (__half2*)(g_dots + (size_t)row * KCB);
#pragma unroll
                    for (int ni = 0; ni < 4; ni++) {
                        const int col = colBase + ni * 8;
                        dst[col >> 1] = __floats2half2_rn(acc[mi][ni][half * 2 + 0],
                                                          acc[mi][ni][half * 2 + 1]);
                    }
                }
            }
        }
    }
}

// ---------------------------------------------------------------------------
// scan: warp per row, single DRAM read, low register pressure.
// Pass A: stream 32 groups/lane; cache per-group min8 in SMEM as fp16.
// Pass B: smem sweep; re-fetch (L2-hit) only groups with min8 < thr.
// count==1 -> argmin directly; 2..8 -> wlc; >8 -> wlf.
// ---------------------------------------------------------------------------
__global__ __launch_bounds__(256)
void vq_scan_kernel() {
    __shared__ __half sg[8][GRP_PER_LANE * 32];   // 16 KB: per-warp group-min cache
    __shared__ int scnt[8];
    const int w    = threadIdx.x >> 5;
    const int lane = threadIdx.x & 31;
    const int row  = blockIdx.x * 8 + w;
    const uint4* dp = (const uint4*)(g_dots + (size_t)row * KCB);

    // ---- pass A: stream + per-group min8 cached in smem ----
    __half2 m2 = __float2half2_rn(6.0e4f);
#pragma unroll 4
    for (int j = 0; j < GRP_PER_LANE; j++) {
        const uint4 u = dp[lane + j * 32];
        const __half2 h0 = *(const __half2*)&u.x;
        const __half2 h1 = *(const __half2*)&u.y;
        const __half2 h2 = *(const __half2*)&u.z;
        const __half2 h3 = *(const __half2*)&u.w;
        const __half2 g2 = __hmin2(__hmin2(h0, h1), __hmin2(h2, h3));
        sg[w][j * 32 + lane] = __hmin(__low2half(g2), __high2half(g2));
        m2 = __hmin2(m2, g2);
    }
    float minv = fminf(__low2float(m2), __high2float(m2));
#pragma unroll
    for (int off = 16; off > 0; off >>= 1)
        minv = fminf(minv, __shfl_xor_sync(0xFFFFFFFFu, minv, off));

    if (lane == 0) scnt[w] = 0;
    __syncwarp();

    // ---- pass B: smem sweep; rare re-fetch + unpack ----
    const float thr = minv + WINDOW;
#pragma unroll 4
    for (int j = 0; j < GRP_PER_LANE; j++) {
        const float g = __half2float(sg[w][j * 32 + lane]);
        if (g < thr) {
            const int gi = lane + j * 32;
            const uint4 u = dp[gi];
            const __half2 hs[4] = { *(const __half2*)&u.x, *(const __half2*)&u.y,
                                    *(const __half2*)&u.z, *(const __half2*)&u.w };
#pragma unroll
            for (int q = 0; q < 4; q++) {
                const float v0 = __low2float(hs[q]), v1 = __high2float(hs[q]);
                if (v0 < thr) {
                    const int p = atomicAdd(&scnt[w], 1);
                    if (p < CAND_CAP) g_cand[(size_t)row * CAND_CAP + p] = gi * 8 + q * 2;
                }
                if (v1 < thr) {
                    const int p = atomicAdd(&scnt[w], 1);
                    if (p < CAND_CAP) g_cand[(size_t)row * CAND_CAP + p] = gi * 8 + q * 2 + 1;
                }
            }
        }
    }
    __syncwarp();

    if (lane == 0) {
        const int total = scnt[w];
        g_ccnt[row] = total;
        if (total > CAND_CAP) {
            const int p = atomicAdd(&g_wlf_count, 1);
            if (p < WLF_CAP) g_wlf[p] = row;
        } else if (total >= 2) {
            const int p = atomicAdd(&g_wlc_count, 1);
            if (p < WLC_CAP) g_wlc[p] = row;
        } else {
            g_argmin[row] = g_cand[(size_t)row * CAND_CAP];  // sole candidate
        }
    }
}

// ---------------------------------------------------------------------------
// refine_cand: exact fp64 rescore of tracked candidates. One warp per row.
// ---------------------------------------------------------------------------
__global__ __launch_bounds__(256)
void vq_refine_cand(const float* __restrict__ z) {
    const int cnt  = min(g_wlc_count, WLC_CAP);
    const int lane = threadIdx.x & 31;
    const int wrp  = threadIdx.x >> 5;

    for (int wi = blockIdx.x * 8 + wrp; wi < cnt; wi += gridDim.x * 8) {
        const int row = g_wlc[wi];
        const int nc = min(g_ccnt[row], CAND_CAP);
        const float* zr = z + (size_t)row * DIM;

        double bestV = 1e300;
        int    bestI = 0x7FFFFFFF;
        for (int j = 0; j < nc; j++) {
            const int k = g_cand[(size_t)row * CAND_CAP + j];
            const float* cw = g_cbT + (size_t)k * DIM;
            double sd = 0.0;
#pragma unroll 4
            for (int d = lane; d < DIM; d += 32)
                sd += (double)cw[d] * (double)zr[d];
#pragma unroll
            for (int off = 16; off > 0; off >>= 1)
                sd += __shfl_down_sync(0xFFFFFFFFu, sd, off);
            sd = __shfl_sync(0xFFFFFFFFu, sd, 0);
            if (sd < bestV || (sd == bestV && k < bestI)) { bestV = sd; bestI = k; }
        }
        if (lane == 0) g_argmin[row] = bestI;
    }
}

// ---------------------------------------------------------------------------
// refine_full: exact pass (fp32 full rescan -> fp64 finish) for overflow rows.
// ---------------------------------------------------------------------------
__global__ __launch_bounds__(256)
void vq_refine_full(const float* __restrict__ A) {
    __shared__ float  zs[DIM];
    __shared__ float  dots[KCB];
    __shared__ float  red[256];
    __shared__ int    cands[MAX_CAND];
    __shared__ double cval[MAX_CAND];
    __shared__ int    ncand;

    const int tid  = threadIdx.x;
    const int lane = tid & 31;
    const int wrp  = tid >> 5;
    const int cnt  = min(g_wlf_count, WLF_CAP);

    for (int wi = blockIdx.x; wi < cnt; wi += gridDim.x) {
        const int row = g_wlf[wi];
#pragma unroll
        for (int i = 0; i < DIM / 256; i++)
            zs[tid + i * 256] = A[(size_t)row * DIM + tid + i * 256];
        if (tid == 0) ncand = 0;
        __syncthreads();

        const float4* z4 = (const float4*)zs;
        float localMin = FLT_MAX;
        for (int k = tid; k < KCB; k += 256) {
            const float4* c4 = (const float4*)(g_cbT + (size_t)k * DIM);
            float sacc = 0.0f;
#pragma unroll 8
            for (int d = 0; d < DIM / 4; d++) {
                const float4 cc = c4[d];
                const float4 zz = z4[d];
                sacc = fmaf(cc.x, zz.x, sacc);
                sacc = fmaf(cc.y, zz.y, sacc);
                sacc = fmaf(cc.z, zz.z, sacc);
                sacc = fmaf(cc.w, zz.w, sacc);
            }
            dots[k] = sacc;
            localMin = fminf(localMin, sacc);
        }
        red[tid] = localMin;
        __syncthreads();
        for (int off = 128; off > 0; off >>= 1) {
            if (tid < off) red[tid] = fminf(red[tid], red[tid + off]);
            __syncthreads();
        }
        const float bmin = red[0];

        for (int k = tid; k < KCB; k += 256) {
            if (dots[k] < bmin + TAU3) {
                const int p = atomicAdd(&ncand, 1);
                if (p < MAX_CAND) cands[p] = k;
            }
        }
        __syncthreads();
        const int nc = min(ncand, MAX_CAND);

        for (int ci = wrp; ci < nc; ci += 8) {
            const int k = cands[ci];
            const float* cbp = g_cbT + (size_t)k * DIM;
            double sd = 0.0;
            for (int d = lane; d < DIM; d += 32)
                sd += (double)cbp[d] * (double)zs[d];
#pragma unroll
            for (int off = 16; off > 0; off >>= 1)
                sd += __shfl_down_sync(0xFFFFFFFFu, sd, off);
            if (lane == 0) cval[ci] = sd;
        }
        __syncthreads();

        if (tid == 0) {
            double bv = cval[0];
            int    bi = cands[0];
            for (int c2 = 1; c2 < nc; c2++) {
                const double v = cval[c2];
                const int    x = cands[c2];
                if (v < bv || (v == bv && x < bi)) { bv = v; bi = x; }
            }
            g_argmin[row] = bi;
        }
        __syncthreads();
    }
}

// ---------------------------------------------------------------------------
// Gather: out[n][:] = g_cbT[argmin[n]][:]
// ---------------------------------------------------------------------------
__global__ void vq_gather_kernel(float* __restrict__ out) {
    const int n = blockIdx.x;
    const int idx = g_argmin[n];
    const float4* src = (const float4*)(g_cbT + (size_t)idx * DIM);
    float4* dst = (float4*)(out + (size_t)n * DIM);
    dst[threadIdx.x] = src[threadIdx.x];
}

// ---------------------------------------------------------------------------
extern "C" void kernel_launch(void* const* d_in, const int* in_sizes, int n_in,
                              void* d_out, int out_size) {
    const float* z  = (const float*)d_in[0];
    const float* cb = (const float*)d_in[1];
    float* out = (float*)d_out;

    cudaFuncSetAttribute(vq_hmma1_kernel, cudaFuncAttributeMaxDynamicSharedMemorySize, H1_SMEM);

    dim3 tgrid(KCB / 32, DIM / 32);
    dim3 tblk(32, 8);
    vq_prep_cb<<<tgrid, tblk>>>(cb);
    vq_prep_z<<<8192, 256>>>(z);

    vq_hmma1_kernel<<<N_ROWS / BM, GEMM_THREADS, H1_SMEM>>>();

    vq_scan_kernel<<<N_ROWS / 8, 256>>>();
    vq_refine_cand<<<2048, 256>>>(z);
    vq_refine_full<<<64, 256>>>(z);
    vq_gather_kernel<<<N_ROWS, 256>>>(out);
}